// round 10
// baseline (speedup 1.0000x reference)
#include <cuda_runtime.h>
#include <cuda_bf16.h>

#define NN 50000
#define EE 800000
#define ETOT (EE + NN)
#define F 128
#define NG 64
#define NOUT 10
#define GEMM_BLOCKS ((NN + 63) / 64)
#define DEG_BLOCKS ((ETOT + 255) / 256)

// ---------------- device scratch (static, no allocation) ----------------
static __device__ __align__(16) int   g_deg[NN];
static __device__ __align__(16) int   g_fill[NN];
static __device__ __align__(16) int   g_rowstart[NN + 1];
static __device__ __align__(16) int2  g_edge[ETOT];      // (src, dst) per CSR slot
static __device__ __align__(16) float g_p[ETOT * 4];     // per-edge exp factors (4 heads)
static __device__ __align__(16) __nv_bfloat16 g_hb[NN * F];  // post-GEMM features (bf16, gather-only)
static __device__ __align__(16) float g_o[NN * F];       // layer-1 aggregated output (fp32)
static __device__ __align__(16) float g_als[NN * 4];
static __device__ __align__(16) float g_ald[NN * 4];
static __device__ __align__(16) float g_pool[NG * F];
static __device__ __align__(16) int   g_cnt[NG];

__device__ __forceinline__ float lrelu(float x) { return x > 0.f ? x : 0.2f * x; }

// ---------------- zero scratch ----------------
__global__ void k_zero() {
    int i = blockIdx.x * blockDim.x + threadIdx.x;
    if (i < NN) { g_deg[i] = 0; g_fill[i] = 0; }
    if (i < NG * F) g_pool[i] = 0.f;
    if (i < NG) g_cnt[i] = 0;
}

// ---------------- raking single-block exclusive scan (1024 thr, 64 elem/thr) ----------------
__global__ void k_scan() {
    const int CH = 64;
    int t = threadIdx.x;
    int wid = t >> 5, lane = t & 31;
    __shared__ int wsum[32];
    int base = t * CH;

    int s = 0;
    if (base + CH <= NN) {
        const int4* p = (const int4*)&g_deg[base];
        #pragma unroll
        for (int k = 0; k < CH / 4; k++) { int4 v = p[k]; s += v.x + v.y + v.z + v.w; }
    } else if (base < NN) {
        for (int k = 0; k < CH && base + k < NN; k++) s += g_deg[base + k];
    }
    int incl = s;
    #pragma unroll
    for (int off = 1; off < 32; off <<= 1) {
        int v = __shfl_up_sync(0xffffffffu, incl, off);
        if (lane >= off) incl += v;
    }
    if (lane == 31) wsum[wid] = incl;
    __syncthreads();
    if (wid == 0) {
        int v = wsum[lane];
        int iv = v;
        #pragma unroll
        for (int off = 1; off < 32; off <<= 1) {
            int u = __shfl_up_sync(0xffffffffu, iv, off);
            if (lane >= off) iv += u;
        }
        wsum[lane] = iv - v;
    }
    __syncthreads();
    int run = wsum[wid] + (incl - s);
    if (base < NN) {
        int lim = (base + CH <= NN) ? CH : (NN - base);
        for (int k = 0; k < lim; k++) {
            int v = g_deg[base + k];
            g_rowstart[base + k] = run;
            run += v;
        }
    }
    if (t == 0) g_rowstart[NN] = ETOT;
}

// ---------------- CSR scatter: one STG.64 per edge ----------------
__global__ void k_scatter(const int* __restrict__ src, const int* __restrict__ dst) {
    int i = blockIdx.x * blockDim.x + threadIdx.x;
    if (i >= ETOT) return;
    int s, d;
    if (i < EE) { s = src[i]; d = dst[i]; }
    else        { s = i - EE; d = s; }
    int slot = g_rowstart[d] + atomicAdd(&g_fill[d], 1);
    g_edge[slot] = make_int2(s, d);
}

// ---------------- GEMM g_hb = bf16(A @ B) + fused coeff epilogue (+ degree tail) ----
__global__ void __launch_bounds__(256) k_gemm(const float* __restrict__ Aext,
                                              const float* __restrict__ B,
                                              const float* __restrict__ asrc,
                                              const float* __restrict__ adst,
                                              const int* __restrict__ dst,
                                              const int* __restrict__ batch,
                                              int use_go) {
    if (blockIdx.x >= GEMM_BLOCKS) {
        int i = (blockIdx.x - GEMM_BLOCKS) * blockDim.x + threadIdx.x;
        if (i < ETOT) {
            int d = (i < EE) ? dst[i] : (i - EE);   // self loops appended
            atomicAdd(&g_deg[d], 1);
        }
        if (i < NN) atomicAdd(&g_cnt[batch[i]], 1);
        return;
    }

    const float* __restrict__ A = use_go ? (const float*)g_o : Aext;
    __shared__ float As[64][16];
    __shared__ float Bs[16][128];
    int t = threadIdx.x;
    int base = blockIdx.x * 64;
    int tx = t & 31;
    int ty = t >> 5;

    float acc[8][4];
    #pragma unroll
    for (int i = 0; i < 8; i++)
        #pragma unroll
        for (int j = 0; j < 4; j++) acc[i][j] = 0.f;

    int lrow = t >> 2;
    int lq = (t & 3) * 4;
    int grow = base + lrow;

    for (int k0 = 0; k0 < 128; k0 += 16) {
        float4 av = make_float4(0.f, 0.f, 0.f, 0.f);
        if (grow < NN) av = *(const float4*)&A[grow * F + k0 + lq];
        *(float4*)&As[lrow][lq] = av;
        int f0 = t * 2;
        #pragma unroll
        for (int u = 0; u < 2; u++) {
            int f = f0 + u;
            int kr = f >> 5;
            int c4 = (f & 31) * 4;
            *(float4*)&Bs[kr][c4] = *(const float4*)&B[(k0 + kr) * F + c4];
        }
        __syncthreads();
        #pragma unroll
        for (int kk = 0; kk < 16; kk++) {
            float4 bv = *(float4*)&Bs[kk][tx * 4];
            #pragma unroll
            for (int i = 0; i < 8; i++) {
                float a = As[ty * 8 + i][kk];
                acc[i][0] = fmaf(a, bv.x, acc[i][0]);
                acc[i][1] = fmaf(a, bv.y, acc[i][1]);
                acc[i][2] = fmaf(a, bv.z, acc[i][2]);
                acc[i][3] = fmaf(a, bv.w, acc[i][3]);
            }
        }
        __syncthreads();
    }

    // epilogue: write bf16 h; reduce als/ald per head from fp32 accumulators
    float wsr[4], wdr[4];
    #pragma unroll
    for (int j = 0; j < 4; j++) { wsr[j] = asrc[tx * 4 + j]; wdr[j] = adst[tx * 4 + j]; }
    int hd = tx >> 3;
    #pragma unroll
    for (int i = 0; i < 8; i++) {
        int r = base + ty * 8 + i;
        float ss = 0.f, sd = 0.f;
        #pragma unroll
        for (int j = 0; j < 4; j++) {
            ss = fmaf(acc[i][j], wsr[j], ss);
            sd = fmaf(acc[i][j], wdr[j], sd);
        }
        #pragma unroll
        for (int off = 4; off; off >>= 1) {
            ss += __shfl_xor_sync(0xffffffffu, ss, off);
            sd += __shfl_xor_sync(0xffffffffu, sd, off);
        }
        if (r < NN) {
            __nv_bfloat162 h01 = __floats2bfloat162_rn(acc[i][0], acc[i][1]);
            __nv_bfloat162 h23 = __floats2bfloat162_rn(acc[i][2], acc[i][3]);
            uint2 pk;
            pk.x = *(unsigned int*)&h01;
            pk.y = *(unsigned int*)&h23;
            *(uint2*)&g_hb[r * F + tx * 4] = pk;   // 8B store: 4 bf16
            if ((tx & 7) == 0) {
                g_als[r * 4 + hd] = ss;
                g_ald[r * 4 + hd] = sd;
            }
        }
    }
}

// ---------------- per-edge exp factors (no max shift; |e| is small by construction) ----------------
__global__ void k_edgep() {
    int i = blockIdx.x * blockDim.x + threadIdx.x;
    if (i >= ETOT) return;
    int2 e = g_edge[i];              // coalesced LDG.64
    float4 as = *(const float4*)&g_als[e.x * 4];
    float4 ad = *(const float4*)&g_ald[e.y * 4];   // CSR-sorted: broadcast-friendly
    float4 p;
    p.x = __expf(lrelu(as.x + ad.x));
    p.y = __expf(lrelu(as.y + ad.y));
    p.z = __expf(lrelu(as.z + ad.z));
    p.w = __expf(lrelu(as.w + ad.w));
    *(float4*)&g_p[i * 4] = p;
}

// ---------------- fused aggregation (warp per dst); bf16 gather, unroll-4 for MLP ----------------
__device__ __forceinline__ float head_sel(float4 p, int lane) {
    float lo = (lane & 8) ? p.y : p.x;
    float hi = (lane & 8) ? p.w : p.z;
    return (lane & 16) ? hi : lo;
}

__global__ void k_agg(const float* __restrict__ bias, const int* __restrict__ batch,
                      int apply_elu, int do_pool) {
    int node = (blockIdx.x * blockDim.x + threadIdx.x) >> 5;
    int lane = threadIdx.x & 31;
    if (node >= NN) return;
    int beg = g_rowstart[node];
    int end = g_rowstart[node + 1];
    int col = lane * 4;

    float zl = 0.f;
    float a0 = 0.f, a1 = 0.f, a2 = 0.f, a3 = 0.f;
    int j = beg;
    for (; j + 4 <= end; j += 4) {
        // issue all independent loads up front (MLP=4 h-gathers + broadcasts)
        int s0 = g_edge[j].x;
        int s1 = g_edge[j + 1].x;
        int s2 = g_edge[j + 2].x;
        int s3 = g_edge[j + 3].x;
        uint2 hv0 = *(const uint2*)&g_hb[s0 * F + col];
        uint2 hv1 = *(const uint2*)&g_hb[s1 * F + col];
        uint2 hv2 = *(const uint2*)&g_hb[s2 * F + col];
        uint2 hv3 = *(const uint2*)&g_hb[s3 * F + col];
        float4 p0 = *(const float4*)&g_p[j * 4];
        float4 p1 = *(const float4*)&g_p[(j + 1) * 4];
        float4 p2 = *(const float4*)&g_p[(j + 2) * 4];
        float4 p3 = *(const float4*)&g_p[(j + 3) * 4];
        float pl0 = head_sel(p0, lane);
        float pl1 = head_sel(p1, lane);
        float pl2 = head_sel(p2, lane);
        float pl3 = head_sel(p3, lane);
        zl += (pl0 + pl1) + (pl2 + pl3);
        float2 x00 = __bfloat1622float2(*(const __nv_bfloat162*)&hv0.x);
        float2 x01 = __bfloat1622float2(*(const __nv_bfloat162*)&hv0.y);
        float2 x10 = __bfloat1622float2(*(const __nv_bfloat162*)&hv1.x);
        float2 x11 = __bfloat1622float2(*(const __nv_bfloat162*)&hv1.y);
        float2 x20 = __bfloat1622float2(*(const __nv_bfloat162*)&hv2.x);
        float2 x21 = __bfloat1622float2(*(const __nv_bfloat162*)&hv2.y);
        float2 x30 = __bfloat1622float2(*(const __nv_bfloat162*)&hv3.x);
        float2 x31 = __bfloat1622float2(*(const __nv_bfloat162*)&hv3.y);
        a0 = fmaf(x00.x, pl0, fmaf(x10.x, pl1, fmaf(x20.x, pl2, fmaf(x30.x, pl3, a0))));
        a1 = fmaf(x00.y, pl0, fmaf(x10.y, pl1, fmaf(x20.y, pl2, fmaf(x30.y, pl3, a1))));
        a2 = fmaf(x01.x, pl0, fmaf(x11.x, pl1, fmaf(x21.x, pl2, fmaf(x31.x, pl3, a2))));
        a3 = fmaf(x01.y, pl0, fmaf(x11.y, pl1, fmaf(x21.y, pl2, fmaf(x31.y, pl3, a3))));
    }
    for (; j < end; j++) {
        int s0 = g_edge[j].x;
        float4 p0 = *(const float4*)&g_p[j * 4];
        uint2 hv0 = *(const uint2*)&g_hb[s0 * F + col];
        float pl0 = head_sel(p0, lane);
        float2 x00 = __bfloat1622float2(*(const __nv_bfloat162*)&hv0.x);
        float2 x01 = __bfloat1622float2(*(const __nv_bfloat162*)&hv0.y);
        zl += pl0;
        a0 = fmaf(x00.x, pl0, a0);
        a1 = fmaf(x00.y, pl0, a1);
        a2 = fmaf(x01.x, pl0, a2);
        a3 = fmaf(x01.y, pl0, a3);
    }

    float4 bv = *(const float4*)&bias[col];
    float inv = 1.f / (zl + 1e-16f);
    float o0 = a0 * inv + bv.x;
    float o1 = a1 * inv + bv.y;
    float o2 = a2 * inv + bv.z;
    float o3 = a3 * inv + bv.w;
    if (apply_elu) {
        o0 = o0 > 0.f ? o0 : __expf(o0) - 1.f;
        o1 = o1 > 0.f ? o1 : __expf(o1) - 1.f;
        o2 = o2 > 0.f ? o2 : __expf(o2) - 1.f;
        o3 = o3 > 0.f ? o3 : __expf(o3) - 1.f;
    }
    if (do_pool) {
        int g = batch[node];
        float* pp = g_pool + g * F + col;
        atomicAdd(&pp[0], o0);
        atomicAdd(&pp[1], o1);
        atomicAdd(&pp[2], o2);
        atomicAdd(&pp[3], o3);
    } else {
        *(float4*)&g_o[node * F + col] = make_float4(o0, o1, o2, o3);
    }
}

// ---------------- final linear + softmax (warp per graph) ----------------
__global__ void k_final(const float* __restrict__ Wl, const float* __restrict__ bl,
                        float* __restrict__ out) {
    int g = (blockIdx.x * blockDim.x + threadIdx.x) >> 5;
    int lane = threadIdx.x & 31;
    if (g >= NG) return;
    float inv = 1.f / fmaxf((float)g_cnt[g], 1.f);
    float logit = -1e30f;
    if (lane < NOUT) {
        float acc = bl[lane];
        for (int c = 0; c < F; c++)
            acc = fmaf(g_pool[g * F + c] * inv, Wl[c * NOUT + lane], acc);
        logit = acc;
    }
    float mx = logit;
    #pragma unroll
    for (int off = 16; off; off >>= 1) mx = fmaxf(mx, __shfl_xor_sync(0xffffffffu, mx, off));
    float ex = (lane < NOUT) ? __expf(logit - mx) : 0.f;
    float s = ex;
    #pragma unroll
    for (int off = 16; off; off >>= 1) s += __shfl_xor_sync(0xffffffffu, s, off);
    if (lane < NOUT) out[g * NOUT + lane] = ex / s;
}

// ---------------- launch ----------------
extern "C" void kernel_launch(void* const* d_in, const int* in_sizes, int n_in,
                              void* d_out, int out_size) {
    const float* x    = (const float*)d_in[0];
    const float* W1   = (const float*)d_in[1];
    const float* a1s  = (const float*)d_in[2];
    const float* a1d  = (const float*)d_in[3];
    const float* b1   = (const float*)d_in[4];
    const float* W2   = (const float*)d_in[5];
    const float* a2s  = (const float*)d_in[6];
    const float* a2d  = (const float*)d_in[7];
    const float* b2   = (const float*)d_in[8];
    const float* Wl   = (const float*)d_in[9];
    const float* bl   = (const float*)d_in[10];
    const int*   ei   = (const int*)d_in[11];
    const int*   batch = (const int*)d_in[12];
    const int* src = ei;
    const int* dst = ei + EE;
    float* out = (float*)d_out;

    int warp_blocks = (NN * 32 + 255) / 256;
    int edge_blocks = (ETOT + 255) / 256;

    // zero scratch, then layer-1 GEMM fused with degree histogram (independent data)
    k_zero<<<(NN + 255) / 256, 256>>>();
    k_gemm<<<GEMM_BLOCKS + DEG_BLOCKS, 256>>>(x, W1, a1s, a1d, dst, batch, 0);

    // CSR finalize
    k_scan<<<1, 1024>>>();
    k_scatter<<<(ETOT + 255) / 256, 256>>>(src, dst);

    // layer 1 edge softmax + aggregation
    k_edgep<<<edge_blocks, 256>>>();
    k_agg<<<warp_blocks, 256>>>(b1, batch, 1, 0);

    // layer 2 (aggregation pools directly)
    k_gemm<<<GEMM_BLOCKS, 256>>>(nullptr, W2, a2s, a2d, dst, batch, 1);
    k_edgep<<<edge_blocks, 256>>>();
    k_agg<<<warp_blocks, 256>>>(b2, batch, 0, 1);

    // head
    k_final<<<(NG * 32 + 255) / 256, 256>>>(Wl, bl, out);
}

// round 11
// speedup vs baseline: 1.3174x; 1.3174x over previous
#include <cuda_runtime.h>

#define NN 50000
#define EE 800000
#define ETOT (EE + NN)
#define F 128
#define NG 64
#define NOUT 10
#define GEMM_BLOCKS ((NN + 63) / 64)
#define DEG_BLOCKS ((ETOT + 255) / 256)

// ---------------- device scratch (static, no allocation) ----------------
static __device__ __align__(16) int   g_deg[NN];
static __device__ __align__(16) int   g_fill[NN];
static __device__ __align__(16) int   g_rowstart[NN + 1];
static __device__ __align__(16) int2  g_edge[ETOT];      // (src, dst) per CSR slot
static __device__ __align__(16) float g_p[ETOT * 4];     // per-edge exp factors (4 heads)
static __device__ __align__(16) float g_h[NN * F];       // post-GEMM features
static __device__ __align__(16) float g_o[NN * F];       // layer-1 aggregated output
static __device__ __align__(16) float g_als[NN * 4];
static __device__ __align__(16) float g_ald[NN * 4];
static __device__ __align__(16) float g_pool[NG * F];
static __device__ __align__(16) int   g_cnt[NG];

__device__ __forceinline__ float lrelu(float x) { return x > 0.f ? x : 0.2f * x; }

// ---------------- zero scratch ----------------
__global__ void k_zero() {
    int i = blockIdx.x * blockDim.x + threadIdx.x;
    if (i < NN) { g_deg[i] = 0; g_fill[i] = 0; }
    if (i < NG * F) g_pool[i] = 0.f;
    if (i < NG) g_cnt[i] = 0;
}

// ---------------- raking single-block exclusive scan (1024 thr, 64 elem/thr) ----------------
__global__ void k_scan() {
    const int CH = 64;
    int t = threadIdx.x;
    int wid = t >> 5, lane = t & 31;
    __shared__ int wsum[32];
    int base = t * CH;

    int s = 0;
    if (base + CH <= NN) {
        const int4* p = (const int4*)&g_deg[base];
        #pragma unroll
        for (int k = 0; k < CH / 4; k++) { int4 v = p[k]; s += v.x + v.y + v.z + v.w; }
    } else if (base < NN) {
        for (int k = 0; k < CH && base + k < NN; k++) s += g_deg[base + k];
    }
    int incl = s;
    #pragma unroll
    for (int off = 1; off < 32; off <<= 1) {
        int v = __shfl_up_sync(0xffffffffu, incl, off);
        if (lane >= off) incl += v;
    }
    if (lane == 31) wsum[wid] = incl;
    __syncthreads();
    if (wid == 0) {
        int v = wsum[lane];
        int iv = v;
        #pragma unroll
        for (int off = 1; off < 32; off <<= 1) {
            int u = __shfl_up_sync(0xffffffffu, iv, off);
            if (lane >= off) iv += u;
        }
        wsum[lane] = iv - v;
    }
    __syncthreads();
    int run = wsum[wid] + (incl - s);
    if (base < NN) {
        int lim = (base + CH <= NN) ? CH : (NN - base);
        for (int k = 0; k < lim; k++) {
            int v = g_deg[base + k];
            g_rowstart[base + k] = run;
            run += v;
        }
    }
    if (t == 0) g_rowstart[NN] = ETOT;
}

// ---------------- CSR scatter: one STG.64 per edge ----------------
__global__ void k_scatter(const int* __restrict__ src, const int* __restrict__ dst) {
    int i = blockIdx.x * blockDim.x + threadIdx.x;
    if (i >= ETOT) return;
    int s, d;
    if (i < EE) { s = src[i]; d = dst[i]; }
    else        { s = i - EE; d = s; }
    int slot = g_rowstart[d] + atomicAdd(&g_fill[d], 1);
    g_edge[slot] = make_int2(s, d);
}

// ---------------- GEMM g_h = A @ B + fused coeff epilogue (+ optional degree tail) ----
// Blocks [0, GEMM_BLOCKS): GEMM (BLOCK_M=64, BK=16, 256 thr, 8x4 per thread).
// Blocks [GEMM_BLOCKS, +DEG_BLOCKS): degree + graph-count histograms (layer 1 only).
__global__ void __launch_bounds__(256) k_gemm(const float* __restrict__ Aext,
                                              const float* __restrict__ B,
                                              const float* __restrict__ asrc,
                                              const float* __restrict__ adst,
                                              const int* __restrict__ dst,
                                              const int* __restrict__ batch,
                                              int use_go) {
    if (blockIdx.x >= GEMM_BLOCKS) {
        int i = (blockIdx.x - GEMM_BLOCKS) * blockDim.x + threadIdx.x;
        if (i < ETOT) {
            int d = (i < EE) ? dst[i] : (i - EE);   // self loops appended
            atomicAdd(&g_deg[d], 1);
        }
        if (i < NN) atomicAdd(&g_cnt[batch[i]], 1);
        return;
    }

    const float* __restrict__ A = use_go ? (const float*)g_o : Aext;
    __shared__ float As[64][16];
    __shared__ float Bs[16][128];
    int t = threadIdx.x;
    int base = blockIdx.x * 64;
    int tx = t & 31;
    int ty = t >> 5;

    float acc[8][4];
    #pragma unroll
    for (int i = 0; i < 8; i++)
        #pragma unroll
        for (int j = 0; j < 4; j++) acc[i][j] = 0.f;

    int lrow = t >> 2;
    int lq = (t & 3) * 4;
    int grow = base + lrow;

    for (int k0 = 0; k0 < 128; k0 += 16) {
        float4 av = make_float4(0.f, 0.f, 0.f, 0.f);
        if (grow < NN) av = *(const float4*)&A[grow * F + k0 + lq];
        *(float4*)&As[lrow][lq] = av;
        int f0 = t * 2;
        #pragma unroll
        for (int u = 0; u < 2; u++) {
            int f = f0 + u;
            int kr = f >> 5;
            int c4 = (f & 31) * 4;
            *(float4*)&Bs[kr][c4] = *(const float4*)&B[(k0 + kr) * F + c4];
        }
        __syncthreads();
        #pragma unroll
        for (int kk = 0; kk < 16; kk++) {
            float4 bv = *(float4*)&Bs[kk][tx * 4];
            #pragma unroll
            for (int i = 0; i < 8; i++) {
                float a = As[ty * 8 + i][kk];
                acc[i][0] = fmaf(a, bv.x, acc[i][0]);
                acc[i][1] = fmaf(a, bv.y, acc[i][1]);
                acc[i][2] = fmaf(a, bv.z, acc[i][2]);
                acc[i][3] = fmaf(a, bv.w, acc[i][3]);
            }
        }
        __syncthreads();
    }

    // epilogue: write h; reduce als/ald per head (heads = lane groups of 8)
    float wsr[4], wdr[4];
    #pragma unroll
    for (int j = 0; j < 4; j++) { wsr[j] = asrc[tx * 4 + j]; wdr[j] = adst[tx * 4 + j]; }
    int hd = tx >> 3;
    #pragma unroll
    for (int i = 0; i < 8; i++) {
        int r = base + ty * 8 + i;
        float ss = 0.f, sd = 0.f;
        #pragma unroll
        for (int j = 0; j < 4; j++) {
            ss = fmaf(acc[i][j], wsr[j], ss);
            sd = fmaf(acc[i][j], wdr[j], sd);
        }
        #pragma unroll
        for (int off = 4; off; off >>= 1) {
            ss += __shfl_xor_sync(0xffffffffu, ss, off);
            sd += __shfl_xor_sync(0xffffffffu, sd, off);
        }
        if (r < NN) {
            *(float4*)&g_h[r * F + tx * 4] =
                make_float4(acc[i][0], acc[i][1], acc[i][2], acc[i][3]);
            if ((tx & 7) == 0) {
                g_als[r * 4 + hd] = ss;
                g_ald[r * 4 + hd] = sd;
            }
        }
    }
}

// ---------------- per-edge exp factors (no max shift; |e| is small by construction) ----------------
__global__ void k_edgep() {
    int i = blockIdx.x * blockDim.x + threadIdx.x;
    if (i >= ETOT) return;
    int2 e = g_edge[i];              // coalesced LDG.64
    float4 as = *(const float4*)&g_als[e.x * 4];
    float4 ad = *(const float4*)&g_ald[e.y * 4];   // CSR-sorted: broadcast-friendly
    float4 p;
    p.x = __expf(lrelu(as.x + ad.x));
    p.y = __expf(lrelu(as.y + ad.y));
    p.z = __expf(lrelu(as.z + ad.z));
    p.w = __expf(lrelu(as.w + ad.w));
    *(float4*)&g_p[i * 4] = p;
}

// ---------------- fused aggregation (warp per dst); fp32 coalesced gather, unroll-4 ----------------
__global__ void k_agg(const float* __restrict__ bias, const int* __restrict__ batch,
                      int apply_elu, int do_pool) {
    int node = (blockIdx.x * blockDim.x + threadIdx.x) >> 5;
    int lane = threadIdx.x & 31;
    if (node >= NN) return;
    int beg = g_rowstart[node];
    int end = g_rowstart[node + 1];

    float z0 = 0.f, z1 = 0.f, z2 = 0.f, z3 = 0.f;
    float a0 = 0.f, a1 = 0.f, a2 = 0.f, a3 = 0.f;
    int j = beg;
    for (; j + 4 <= end; j += 4) {
        int s0 = g_edge[j].x;
        int s1 = g_edge[j + 1].x;
        int s2 = g_edge[j + 2].x;
        int s3 = g_edge[j + 3].x;
        float4 p0 = *(const float4*)&g_p[j * 4];
        float4 p1 = *(const float4*)&g_p[(j + 1) * 4];
        float4 p2 = *(const float4*)&g_p[(j + 2) * 4];
        float4 p3 = *(const float4*)&g_p[(j + 3) * 4];
        const float* h0 = g_h + s0 * F;
        const float* h1 = g_h + s1 * F;
        const float* h2 = g_h + s2 * F;
        const float* h3 = g_h + s3 * F;
        float x00 = h0[lane], x01 = h0[32 + lane], x02 = h0[64 + lane], x03 = h0[96 + lane];
        float x10 = h1[lane], x11 = h1[32 + lane], x12 = h1[64 + lane], x13 = h1[96 + lane];
        float x20 = h2[lane], x21 = h2[32 + lane], x22 = h2[64 + lane], x23 = h2[96 + lane];
        float x30 = h3[lane], x31 = h3[32 + lane], x32 = h3[64 + lane], x33 = h3[96 + lane];
        z0 += (p0.x + p1.x) + (p2.x + p3.x);
        z1 += (p0.y + p1.y) + (p2.y + p3.y);
        z2 += (p0.z + p1.z) + (p2.z + p3.z);
        z3 += (p0.w + p1.w) + (p2.w + p3.w);
        a0 = fmaf(x00, p0.x, fmaf(x10, p1.x, fmaf(x20, p2.x, fmaf(x30, p3.x, a0))));
        a1 = fmaf(x01, p0.y, fmaf(x11, p1.y, fmaf(x21, p2.y, fmaf(x31, p3.y, a1))));
        a2 = fmaf(x02, p0.z, fmaf(x12, p1.z, fmaf(x22, p2.z, fmaf(x32, p3.z, a2))));
        a3 = fmaf(x03, p0.w, fmaf(x13, p1.w, fmaf(x23, p2.w, fmaf(x33, p3.w, a3))));
    }
    for (; j < end; j++) {
        int s0 = g_edge[j].x;
        float4 p0 = *(const float4*)&g_p[j * 4];
        const float* h0 = g_h + s0 * F;
        z0 += p0.x; z1 += p0.y; z2 += p0.z; z3 += p0.w;
        a0 = fmaf(h0[lane],      p0.x, a0);
        a1 = fmaf(h0[32 + lane], p0.y, a1);
        a2 = fmaf(h0[64 + lane], p0.z, a2);
        a3 = fmaf(h0[96 + lane], p0.w, a3);
    }

    float o0 = a0 / (z0 + 1e-16f) + bias[lane];
    float o1 = a1 / (z1 + 1e-16f) + bias[32 + lane];
    float o2 = a2 / (z2 + 1e-16f) + bias[64 + lane];
    float o3 = a3 / (z3 + 1e-16f) + bias[96 + lane];
    if (apply_elu) {
        o0 = o0 > 0.f ? o0 : __expf(o0) - 1.f;
        o1 = o1 > 0.f ? o1 : __expf(o1) - 1.f;
        o2 = o2 > 0.f ? o2 : __expf(o2) - 1.f;
        o3 = o3 > 0.f ? o3 : __expf(o3) - 1.f;
    }
    if (do_pool) {
        int g = batch[node];
        float* pp = g_pool + g * F;
        atomicAdd(&pp[lane],      o0);
        atomicAdd(&pp[32 + lane], o1);
        atomicAdd(&pp[64 + lane], o2);
        atomicAdd(&pp[96 + lane], o3);
    } else {
        float* op = g_o + node * F;
        op[lane]      = o0;
        op[32 + lane] = o1;
        op[64 + lane] = o2;
        op[96 + lane] = o3;
    }
}

// ---------------- final linear + softmax (warp per graph) ----------------
__global__ void k_final(const float* __restrict__ Wl, const float* __restrict__ bl,
                        float* __restrict__ out) {
    int g = (blockIdx.x * blockDim.x + threadIdx.x) >> 5;
    int lane = threadIdx.x & 31;
    if (g >= NG) return;
    float inv = 1.f / fmaxf((float)g_cnt[g], 1.f);
    float logit = -1e30f;
    if (lane < NOUT) {
        float acc = bl[lane];
        for (int c = 0; c < F; c++)
            acc = fmaf(g_pool[g * F + c] * inv, Wl[c * NOUT + lane], acc);
        logit = acc;
    }
    float mx = logit;
    #pragma unroll
    for (int off = 16; off; off >>= 1) mx = fmaxf(mx, __shfl_xor_sync(0xffffffffu, mx, off));
    float ex = (lane < NOUT) ? __expf(logit - mx) : 0.f;
    float s = ex;
    #pragma unroll
    for (int off = 16; off; off >>= 1) s += __shfl_xor_sync(0xffffffffu, s, off);
    if (lane < NOUT) out[g * NOUT + lane] = ex / s;
}

// ---------------- launch ----------------
extern "C" void kernel_launch(void* const* d_in, const int* in_sizes, int n_in,
                              void* d_out, int out_size) {
    const float* x    = (const float*)d_in[0];
    const float* W1   = (const float*)d_in[1];
    const float* a1s  = (const float*)d_in[2];
    const float* a1d  = (const float*)d_in[3];
    const float* b1   = (const float*)d_in[4];
    const float* W2   = (const float*)d_in[5];
    const float* a2s  = (const float*)d_in[6];
    const float* a2d  = (const float*)d_in[7];
    const float* b2   = (const float*)d_in[8];
    const float* Wl   = (const float*)d_in[9];
    const float* bl   = (const float*)d_in[10];
    const int*   ei   = (const int*)d_in[11];
    const int*   batch = (const int*)d_in[12];
    const int* src = ei;
    const int* dst = ei + EE;
    float* out = (float*)d_out;

    int warp_blocks = (NN * 32 + 255) / 256;
    int edge_blocks = (ETOT + 255) / 256;

    // zero scratch, then layer-1 GEMM fused with degree histogram (independent data)
    k_zero<<<(NN + 255) / 256, 256>>>();
    k_gemm<<<GEMM_BLOCKS + DEG_BLOCKS, 256>>>(x, W1, a1s, a1d, dst, batch, 0);

    // CSR finalize
    k_scan<<<1, 1024>>>();
    k_scatter<<<(ETOT + 255) / 256, 256>>>(src, dst);

    // layer 1 edge softmax + aggregation
    k_edgep<<<edge_blocks, 256>>>();
    k_agg<<<warp_blocks, 256>>>(b1, batch, 1, 0);

    // layer 2 (aggregation pools directly)
    k_gemm<<<GEMM_BLOCKS, 256>>>(nullptr, W2, a2s, a2d, dst, batch, 1);
    k_edgep<<<edge_blocks, 256>>>();
    k_agg<<<warp_blocks, 256>>>(b2, batch, 0, 1);

    // head
    k_final<<<(NG * 32 + 255) / 256, 256>>>(Wl, bl, out);
}

// round 15
// speedup vs baseline: 1.7774x; 1.3492x over previous
#include <cuda_runtime.h>
#include <cuda_bf16.h>

#define NN 50000
#define EE 800000
#define ETOT (EE + NN)
#define F 128
#define NG 64
#define NOUT 10
#define GEMM_BLOCKS ((NN + 63) / 64)
#define DEG_BLOCKS ((ETOT + 255) / 256)
#define AS_STRIDE 136
#define BS_STRIDE 72

// ---------------- device scratch (static, no allocation) ----------------
static __device__ __align__(16) int   g_deg[NN];
static __device__ __align__(16) int   g_fill[NN];
static __device__ __align__(16) int   g_rowstart[NN + 1];
static __device__ __align__(16) int2  g_edge[ETOT];      // (src, dst) per CSR slot
static __device__ __align__(16) float g_p[ETOT * 4];     // per-edge exp factors (4 heads)
static __device__ __align__(16) float g_h[NN * F];       // post-GEMM features (fp32)
static __device__ __align__(16) float g_o[NN * F];       // layer-1 aggregated output
static __device__ __align__(16) float g_als[NN * 4];
static __device__ __align__(16) float g_ald[NN * 4];
static __device__ __align__(16) float g_pool[NG * F];
static __device__ __align__(16) int   g_cnt[NG];
static __device__ __align__(16) __nv_bfloat16 g_W1t[F * F];  // W1^T bf16 [n][k]
static __device__ __align__(16) __nv_bfloat16 g_W2t[F * F];  // W2^T bf16 [n][k]

__device__ __forceinline__ float lrelu(float x) { return x > 0.f ? x : 0.2f * x; }

__device__ __forceinline__ void mma_bf16(float* c, const unsigned int* a,
                                         const unsigned int* b) {
    asm volatile(
        "mma.sync.aligned.m16n8k16.row.col.f32.bf16.bf16.f32 "
        "{%0,%1,%2,%3}, {%4,%5,%6,%7}, {%8,%9}, {%0,%1,%2,%3};"
        : "+f"(c[0]), "+f"(c[1]), "+f"(c[2]), "+f"(c[3])
        : "r"(a[0]), "r"(a[1]), "r"(a[2]), "r"(a[3]), "r"(b[0]), "r"(b[1]));
}

// ---------------- zero scratch + W transpose->bf16 ----------------
__global__ void k_zero(const float* __restrict__ W1, const float* __restrict__ W2) {
    int i = blockIdx.x * blockDim.x + threadIdx.x;
    if (i < NN) { g_deg[i] = 0; g_fill[i] = 0; }
    if (i < NG * F) g_pool[i] = 0.f;
    if (i < NG) g_cnt[i] = 0;
    if (i < F * F) {
        int n = i >> 7, k = i & 127;
        g_W1t[n * F + k] = __float2bfloat16(W1[k * F + n]);
    } else if (i < 2 * F * F) {
        int j = i - F * F;
        int n = j >> 7, k = j & 127;
        g_W2t[n * F + k] = __float2bfloat16(W2[k * F + n]);
    }
}

// ---------------- raking single-block exclusive scan (1024 thr, 64 elem/thr) ----------------
__global__ void k_scan() {
    const int CH = 64;
    int t = threadIdx.x;
    int wid = t >> 5, lane = t & 31;
    __shared__ int wsum[32];
    int base = t * CH;

    int s = 0;
    if (base + CH <= NN) {
        const int4* p = (const int4*)&g_deg[base];
        #pragma unroll
        for (int k = 0; k < CH / 4; k++) { int4 v = p[k]; s += v.x + v.y + v.z + v.w; }
    } else if (base < NN) {
        for (int k = 0; k < CH && base + k < NN; k++) s += g_deg[base + k];
    }
    int incl = s;
    #pragma unroll
    for (int off = 1; off < 32; off <<= 1) {
        int v = __shfl_up_sync(0xffffffffu, incl, off);
        if (lane >= off) incl += v;
    }
    if (lane == 31) wsum[wid] = incl;
    __syncthreads();
    if (wid == 0) {
        int v = wsum[lane];
        int iv = v;
        #pragma unroll
        for (int off = 1; off < 32; off <<= 1) {
            int u = __shfl_up_sync(0xffffffffu, iv, off);
            if (lane >= off) iv += u;
        }
        wsum[lane] = iv - v;
    }
    __syncthreads();
    int run = wsum[wid] + (incl - s);
    if (base < NN) {
        int lim = (base + CH <= NN) ? CH : (NN - base);
        for (int k = 0; k < lim; k++) {
            int v = g_deg[base + k];
            g_rowstart[base + k] = run;
            run += v;
        }
    }
    if (t == 0) g_rowstart[NN] = ETOT;
}

// ---------------- CSR scatter: one STG.64 per edge ----------------
__global__ void k_scatter(const int* __restrict__ src, const int* __restrict__ dst) {
    int i = blockIdx.x * blockDim.x + threadIdx.x;
    if (i >= ETOT) return;
    int s, d;
    if (i < EE) { s = src[i]; d = dst[i]; }
    else        { s = i - EE; d = s; }
    int slot = g_rowstart[d] + atomicAdd(&g_fill[d], 1);
    g_edge[slot] = make_int2(s, d);
}

// ---------------- tensor-core GEMM g_h = A @ W + fused coeff epilogue (+ degree tail) ----
// Blocks [0, GEMM_BLOCKS): 64 rows x 128 cols, bf16 mma.m16n8k16, fp32 accum.
// Blocks [GEMM_BLOCKS, +DEG_BLOCKS): degree + graph-count histograms (layer 1 only).
__global__ void __launch_bounds__(256) k_gemm(const float* __restrict__ Aext,
                                              const float* __restrict__ asrc,
                                              const float* __restrict__ adst,
                                              const int* __restrict__ dst,
                                              const int* __restrict__ batch,
                                              int use_go) {
    if (blockIdx.x >= GEMM_BLOCKS) {
        int i = (blockIdx.x - GEMM_BLOCKS) * blockDim.x + threadIdx.x;
        if (i < ETOT) {
            int d = (i < EE) ? dst[i] : (i - EE);   // self loops appended
            atomicAdd(&g_deg[d], 1);
        }
        if (i < NN) atomicAdd(&g_cnt[batch[i]], 1);
        return;
    }

    const float* __restrict__ A = use_go ? (const float*)g_o : Aext;
    const __nv_bfloat16* __restrict__ Wt = use_go ? g_W2t : g_W1t;

    __shared__ __align__(16) unsigned short As16[64 * AS_STRIDE];   // bf16 A tile [m][k]
    __shared__ __align__(16) unsigned short Bs16[128 * BS_STRIDE];  // bf16 W^T half [n][k64]

    int t = threadIdx.x;
    int lane = t & 31;
    int w = t >> 5;
    int wm = w >> 2;            // 0..1  (32-row slice)
    int wn = w & 3;             // 0..3  (32-col slice == head)
    int lg = lane >> 2;         // 0..7
    int lq = lane & 3;          // 0..3
    int base = blockIdx.x * 64;

    // stage A: 64x128 fp32 -> bf16 smem
    {
        int row = t >> 2;
        int grow = base + row;
        #pragma unroll
        for (int i = 0; i < 8; i++) {
            int c4 = (t & 3) * 4 + i * 16;
            float4 av = make_float4(0.f, 0.f, 0.f, 0.f);
            if (grow < NN) av = *(const float4*)&A[grow * F + c4];
            __nv_bfloat162 p01 = __floats2bfloat162_rn(av.x, av.y);
            __nv_bfloat162 p23 = __floats2bfloat162_rn(av.z, av.w);
            *(unsigned int*)&As16[row * AS_STRIDE + c4]     = *(unsigned int*)&p01;
            *(unsigned int*)&As16[row * AS_STRIDE + c4 + 2] = *(unsigned int*)&p23;
        }
    }

    float c[2][4][4];
    #pragma unroll
    for (int mt = 0; mt < 2; mt++)
        #pragma unroll
        for (int nt = 0; nt < 4; nt++)
            #pragma unroll
            for (int q = 0; q < 4; q++) c[mt][nt][q] = 0.f;

    #pragma unroll
    for (int kh = 0; kh < 2; kh++) {
        __syncthreads();   // A staged / previous Bs consumed
        // stage Bs: W^T [n=128][k=64] bf16, coalesced uint4
        {
            int n = t >> 1;
            int k0 = (t & 1) * 32;
            #pragma unroll
            for (int j = 0; j < 4; j++) {
                uint4 v = *(const uint4*)&Wt[n * F + kh * 64 + k0 + j * 8];
                *(uint4*)&Bs16[n * BS_STRIDE + k0 + j * 8] = v;
            }
        }
        __syncthreads();
        #pragma unroll
        for (int ks = 0; ks < 4; ks++) {
            int ak = kh * 64 + ks * 16 + lq * 2;    // A col (full K index)
            int bk = ks * 16 + lq * 2;              // B col within half
            unsigned int a[2][4];
            #pragma unroll
            for (int mt = 0; mt < 2; mt++) {
                int r0 = wm * 32 + mt * 16 + lg;
                a[mt][0] = *(const unsigned int*)&As16[r0 * AS_STRIDE + ak];
                a[mt][1] = *(const unsigned int*)&As16[(r0 + 8) * AS_STRIDE + ak];
                a[mt][2] = *(const unsigned int*)&As16[r0 * AS_STRIDE + ak + 8];
                a[mt][3] = *(const unsigned int*)&As16[(r0 + 8) * AS_STRIDE + ak + 8];
            }
            unsigned int b[4][2];
            #pragma unroll
            for (int nt = 0; nt < 4; nt++) {
                int n0 = wn * 32 + nt * 8 + lg;
                b[nt][0] = *(const unsigned int*)&Bs16[n0 * BS_STRIDE + bk];
                b[nt][1] = *(const unsigned int*)&Bs16[n0 * BS_STRIDE + bk + 8];
            }
            #pragma unroll
            for (int mt = 0; mt < 2; mt++)
                #pragma unroll
                for (int nt = 0; nt < 4; nt++)
                    mma_bf16(c[mt][nt], a[mt], b[nt]);
        }
    }

    // epilogue: write h (fp32) + per-head coefficient reduction (head == wn)
    float ws0[4], ws1[4], wd0[4], wd1[4];
    #pragma unroll
    for (int nt = 0; nt < 4; nt++) {
        int col = wn * 32 + nt * 8 + lq * 2;
        ws0[nt] = asrc[col];     ws1[nt] = asrc[col + 1];
        wd0[nt] = adst[col];     wd1[nt] = adst[col + 1];
    }
    #pragma unroll
    for (int mt = 0; mt < 2; mt++) {
        #pragma unroll
        for (int half = 0; half < 2; half++) {
            int r = base + wm * 32 + mt * 16 + lg + half * 8;
            float ss = 0.f, sd = 0.f;
            #pragma unroll
            for (int nt = 0; nt < 4; nt++) {
                float clo = c[mt][nt][half * 2];
                float chi = c[mt][nt][half * 2 + 1];
                ss = fmaf(clo, ws0[nt], fmaf(chi, ws1[nt], ss));
                sd = fmaf(clo, wd0[nt], fmaf(chi, wd1[nt], sd));
            }
            ss += __shfl_xor_sync(0xffffffffu, ss, 1);
            ss += __shfl_xor_sync(0xffffffffu, ss, 2);
            sd += __shfl_xor_sync(0xffffffffu, sd, 1);
            sd += __shfl_xor_sync(0xffffffffu, sd, 2);
            if (r < NN) {
                #pragma unroll
                for (int nt = 0; nt < 4; nt++) {
                    int col = wn * 32 + nt * 8 + lq * 2;
                    *(float2*)&g_h[r * F + col] =
                        make_float2(c[mt][nt][half * 2], c[mt][nt][half * 2 + 1]);
                }
                if (lq == 0) {
                    g_als[r * 4 + wn] = ss;
                    g_ald[r * 4 + wn] = sd;
                }
            }
        }
    }
}

// ---------------- per-edge exp factors (no max shift; |e| is small by construction) ----------------
__global__ void k_edgep() {
    int i = blockIdx.x * blockDim.x + threadIdx.x;
    if (i >= ETOT) return;
    int2 e = g_edge[i];              // coalesced LDG.64
    float4 as = *(const float4*)&g_als[e.x * 4];
    float4 ad = *(const float4*)&g_ald[e.y * 4];   // CSR-sorted: broadcast-friendly
    float4 p;
    p.x = __expf(lrelu(as.x + ad.x));
    p.y = __expf(lrelu(as.y + ad.y));
    p.z = __expf(lrelu(as.z + ad.z));
    p.w = __expf(lrelu(as.w + ad.w));
    *(float4*)&g_p[i * 4] = p;
}

// ---------------- fused aggregation (warp per dst); fp32 gather, unroll-2 (R8 layout) ----------------
__global__ void k_agg(const float* __restrict__ bias, const int* __restrict__ batch,
                      int apply_elu, int do_pool) {
    int node = (blockIdx.x * blockDim.x + threadIdx.x) >> 5;
    int lane = threadIdx.x & 31;
    if (node >= NN) return;
    int beg = g_rowstart[node];
    int end = g_rowstart[node + 1];

    float z0 = 0.f, z1 = 0.f, z2 = 0.f, z3 = 0.f;
    float a0 = 0.f, a1 = 0.f, a2 = 0.f, a3 = 0.f;
    int j = beg;
    for (; j + 2 <= end; j += 2) {
        int s0 = g_edge[j].x;
        int s1 = g_edge[j + 1].x;
        float4 p0 = *(const float4*)&g_p[j * 4];
        float4 p1 = *(const float4*)&g_p[(j + 1) * 4];
        const float* h0 = g_h + s0 * F;
        const float* h1 = g_h + s1 * F;
        float x00 = h0[lane], x01 = h0[32 + lane], x02 = h0[64 + lane], x03 = h0[96 + lane];
        float x10 = h1[lane], x11 = h1[32 + lane], x12 = h1[64 + lane], x13 = h1[96 + lane];
        z0 += p0.x + p1.x; z1 += p0.y + p1.y; z2 += p0.z + p1.z; z3 += p0.w + p1.w;
        a0 = fmaf(x00, p0.x, fmaf(x10, p1.x, a0));
        a1 = fmaf(x01, p0.y, fmaf(x11, p1.y, a1));
        a2 = fmaf(x02, p0.z, fmaf(x12, p1.z, a2));
        a3 = fmaf(x03, p0.w, fmaf(x13, p1.w, a3));
    }
    if (j < end) {
        int s0 = g_edge[j].x;
        float4 p0 = *(const float4*)&g_p[j * 4];
        const float* h0 = g_h + s0 * F;
        z0 += p0.x; z1 += p0.y; z2 += p0.z; z3 += p0.w;
        a0 = fmaf(h0[lane],      p0.x, a0);
        a1 = fmaf(h0[32 + lane], p0.y, a1);
        a2 = fmaf(h0[64 + lane], p0.z, a2);
        a3 = fmaf(h0[96 + lane], p0.w, a3);
    }

    float o0 = a0 / (z0 + 1e-16f) + bias[lane];
    float o1 = a1 / (z1 + 1e-16f) + bias[32 + lane];
    float o2 = a2 / (z2 + 1e-16f) + bias[64 + lane];
    float o3 = a3 / (z3 + 1e-16f) + bias[96 + lane];
    if (apply_elu) {
        o0 = o0 > 0.f ? o0 : __expf(o0) - 1.f;
        o1 = o1 > 0.f ? o1 : __expf(o1) - 1.f;
        o2 = o2 > 0.f ? o2 : __expf(o2) - 1.f;
        o3 = o3 > 0.f ? o3 : __expf(o3) - 1.f;
    }
    if (do_pool) {
        int g = batch[node];
        float* pp = g_pool + g * F;
        atomicAdd(&pp[lane],      o0);
        atomicAdd(&pp[32 + lane], o1);
        atomicAdd(&pp[64 + lane], o2);
        atomicAdd(&pp[96 + lane], o3);
    } else {
        float* op = g_o + node * F;
        op[lane]      = o0;
        op[32 + lane] = o1;
        op[64 + lane] = o2;
        op[96 + lane] = o3;
    }
}

// ---------------- final linear + softmax (warp per graph) ----------------
__global__ void k_final(const float* __restrict__ Wl, const float* __restrict__ bl,
                        float* __restrict__ out) {
    int g = (blockIdx.x * blockDim.x + threadIdx.x) >> 5;
    int lane = threadIdx.x & 31;
    if (g >= NG) return;
    float inv = 1.f / fmaxf((float)g_cnt[g], 1.f);
    float logit = -1e30f;
    if (lane < NOUT) {
        float acc = bl[lane];
        for (int c = 0; c < F; c++)
            acc = fmaf(g_pool[g * F + c] * inv, Wl[c * NOUT + lane], acc);
        logit = acc;
    }
    float mx = logit;
    #pragma unroll
    for (int off = 16; off; off >>= 1) mx = fmaxf(mx, __shfl_xor_sync(0xffffffffu, mx, off));
    float ex = (lane < NOUT) ? __expf(logit - mx) : 0.f;
    float s = ex;
    #pragma unroll
    for (int off = 16; off; off >>= 1) s += __shfl_xor_sync(0xffffffffu, s, off);
    if (lane < NOUT) out[g * NOUT + lane] = ex / s;
}

// ---------------- launch ----------------
extern "C" void kernel_launch(void* const* d_in, const int* in_sizes, int n_in,
                              void* d_out, int out_size) {
    const float* x    = (const float*)d_in[0];
    const float* W1   = (const float*)d_in[1];
    const float* a1s  = (const float*)d_in[2];
    const float* a1d  = (const float*)d_in[3];
    const float* b1   = (const float*)d_in[4];
    const float* W2   = (const float*)d_in[5];
    const float* a2s  = (const float*)d_in[6];
    const float* a2d  = (const float*)d_in[7];
    const float* b2   = (const float*)d_in[8];
    const float* Wl   = (const float*)d_in[9];
    const float* bl   = (const float*)d_in[10];
    const int*   ei   = (const int*)d_in[11];
    const int*   batch = (const int*)d_in[12];
    const int* src = ei;
    const int* dst = ei + EE;
    float* out = (float*)d_out;

    int warp_blocks = (NN * 32 + 255) / 256;
    int edge_blocks = (ETOT + 255) / 256;

    // zero scratch + W->bf16 transpose, then layer-1 GEMM fused with degree histogram
    k_zero<<<(NN + 255) / 256, 256>>>(W1, W2);
    k_gemm<<<GEMM_BLOCKS + DEG_BLOCKS, 256>>>(x, a1s, a1d, dst, batch, 0);

    // CSR finalize
    k_scan<<<1, 1024>>>();
    k_scatter<<<(ETOT + 255) / 256, 256>>>(src, dst);

    // layer 1 edge softmax + aggregation
    k_edgep<<<edge_blocks, 256>>>();
    k_agg<<<warp_blocks, 256>>>(b1, batch, 1, 0);

    // layer 2 (aggregation pools directly)
    k_gemm<<<GEMM_BLOCKS, 256>>>(nullptr, a2s, a2d, dst, batch, 1);
    k_edgep<<<edge_blocks, 256>>>();
    k_agg<<<warp_blocks, 256>>>(b2, batch, 0, 1);

    // head
    k_final<<<(NG * 32 + 255) / 256, 256>>>(Wl, bl, out);
}